// round 2
// baseline (speedup 1.0000x reference)
#include <cuda_runtime.h>

#define NTOK 65536
#define EDIM 256
#define NE   1024

#define OFF_ZQ   0
#define OFF_LOSS 16777216
#define OFF_IDX  16777217
#define OFF_SAMP 16842753
#define OFF_MCD  16844801
#define OFF_MCV  16844802

static __device__ float  g_zz[NTOK];
static __device__ float  g_ee[NE];
static __device__ int    g_idx[NTOK];
static __device__ float  g_cd[NE * NE];
static __device__ double g_loss_acc;
static __device__ double g_min2_acc;
static __device__ double g_var_acc;

// Packed dual-fp32 FMA (Blackwell; PTX-only, not emitted by nvcc from C++)
__device__ __forceinline__ unsigned long long ffma2(unsigned long long a,
                                                    unsigned long long b,
                                                    unsigned long long c) {
    unsigned long long d;
    asm("fma.rn.f32x2 %0, %1, %2, %3;" : "=l"(d) : "l"(a), "l"(b), "l"(c));
    return d;
}

// ---------------------------------------------------------------------------
__global__ void init_kernel(float* __restrict__ out) {
    int i = blockIdx.x * blockDim.x + threadIdx.x;
    if (i < 2048) out[OFF_SAMP + i] = 0.0f;
    if (i == 0) { g_loss_acc = 0.0; g_min2_acc = 0.0; g_var_acc = 0.0; }
}

// ee[n] = sum_c emb[n,c]^2
__global__ void ee_kernel(const float* __restrict__ emb) {
    int n = blockIdx.x * blockDim.x + threadIdx.x;
    if (n >= NE) return;
    const float* r = emb + (size_t)n * EDIM;
    float acc = 0.0f;
    for (int c = 0; c < EDIM; c++) { float v = r[c]; acc = fmaf(v, v, acc); }
    g_ee[n] = acc;
}

// zz[t] = sum_c z[b,c,s]^2   (t = b*32768 + s)
__global__ void zz_kernel(const float* __restrict__ z) {
    int t = blockIdx.x * blockDim.x + threadIdx.x;
    int b = t >> 15, s = t & 32767;
    const float* base = z + ((size_t)b << 23) + s;
    float acc = 0.0f;
#pragma unroll 8
    for (int c = 0; c < EDIM; c++) {
        float v = base[(size_t)c << 15];
        acc = fmaf(v, v, acc);
    }
    g_zz[t] = acc;
}

// ---------------------------------------------------------------------------
// Distance GEMM + argmin. Block: 128 tokens x all 1024 codes (8 tiles of 128).
// 128 threads: tx in [0,8) owns 16 codes, ty in [0,16) owns 8 tokens.
// Accumulators packed as f32x2 (token pairs).
__global__ void __launch_bounds__(128, 3)
dist_kernel(const float* __restrict__ z, const float* __restrict__ emb,
            float* __restrict__ out) {
    __shared__ float As[16][128];   // [k][token]
    __shared__ float Bs[16][128];   // [k][code]
    __shared__ float rv[128][8];
    __shared__ int   ri[128][8];

    int tid = threadIdx.x;
    int tx = tid & 7;
    int ty = tid >> 3;
    int t0 = blockIdx.x * 128;
    int b = t0 >> 15, s0 = t0 & 32767;
    const float* zb = z + ((size_t)b << 23) + s0;

    float tzz[8];
#pragma unroll
    for (int i = 0; i < 8; i++) tzz[i] = g_zz[t0 + ty * 8 + i];

    float best[8];
    int   bidx[8];
#pragma unroll
    for (int i = 0; i < 8; i++) { best[i] = 3.4e38f; bidx[i] = 0; }

    int la_k = tid >> 3;         // A-load row 0..15
    int la_s = (tid & 7) * 16;   // A-load col start

    for (int nt = 0; nt < 8; nt++) {
        int n0 = nt * 128;
        unsigned long long acc[4][16];
#pragma unroll
        for (int p = 0; p < 4; p++)
#pragma unroll
            for (int j = 0; j < 16; j++) acc[p][j] = 0ull;

        for (int kc = 0; kc < 16; kc++) {
            int k0 = kc * 16;
            __syncthreads();
            // A: z[k0+kk, s0..s0+127]  (tokens contiguous in memory)
            {
                const float4* src =
                    (const float4*)(zb + ((size_t)(k0 + la_k) << 15) + la_s);
                float4* dst = (float4*)&As[la_k][la_s];
#pragma unroll
                for (int q = 0; q < 4; q++) dst[q] = src[q];
            }
            // B: emb rows n0+tid, 16 k values, transposed into Bs[k][n]
            {
                const float4* src =
                    (const float4*)(emb + (size_t)(n0 + tid) * EDIM + k0);
#pragma unroll
                for (int q = 0; q < 4; q++) {
                    float4 v = src[q];
                    Bs[q * 4 + 0][tid] = v.x;
                    Bs[q * 4 + 1][tid] = v.y;
                    Bs[q * 4 + 2][tid] = v.z;
                    Bs[q * 4 + 3][tid] = v.w;
                }
            }
            __syncthreads();
#pragma unroll
            for (int kk = 0; kk < 16; kk++) {
                unsigned long long a2[4];
                const float2* arow = (const float2*)&As[kk][ty * 8];
#pragma unroll
                for (int p = 0; p < 4; p++) {
                    float2 av = arow[p];
                    a2[p] = *(unsigned long long*)&av;
                }
#pragma unroll
                for (int j = 0; j < 16; j++) {
                    int jj = (j + 2 * tx) & 15;   // bank-conflict-free permutation
                    unsigned int bb = __float_as_uint(Bs[kk][tx * 16 + jj]);
                    unsigned long long b2 = ((unsigned long long)bb << 32) | bb;
#pragma unroll
                    for (int p = 0; p < 4; p++)
                        acc[p][j] = ffma2(a2[p], b2, acc[p][j]);
                }
            }
        }
        // epilogue: d = fl(fl(zz+ee) - 2*dot), argmin with lowest-index tiebreak
#pragma unroll
        for (int j = 0; j < 16; j++) {
            int jj = (j + 2 * tx) & 15;
            int n = n0 + tx * 16 + jj;
            float ev = g_ee[n];
#pragma unroll
            for (int p = 0; p < 4; p++) {
                float2 av = *(float2*)&acc[p][j];
                {
                    int i = 2 * p;
                    float d = __fadd_rn(__fadd_rn(tzz[i], ev), -2.0f * av.x);
                    if (d < best[i] || (d == best[i] && n < bidx[i])) {
                        best[i] = d; bidx[i] = n;
                    }
                }
                {
                    int i = 2 * p + 1;
                    float d = __fadd_rn(__fadd_rn(tzz[i], ev), -2.0f * av.y);
                    if (d < best[i] || (d == best[i] && n < bidx[i])) {
                        best[i] = d; bidx[i] = n;
                    }
                }
            }
        }
    }

    __syncthreads();
#pragma unroll
    for (int i = 0; i < 8; i++) {
        rv[ty * 8 + i][tx] = best[i];
        ri[ty * 8 + i][tx] = bidx[i];
    }
    __syncthreads();
    {
        float bv = rv[tid][0];
        int   bi = ri[tid][0];
#pragma unroll
        for (int x = 1; x < 8; x++) {
            float v = rv[tid][x];
            int   id = ri[tid][x];
            if (v < bv || (v == bv && id < bi)) { bv = v; bi = id; }
        }
        int t = t0 + tid;
        g_idx[t] = bi;
        out[OFF_IDX + t] = (float)bi;
        out[OFF_SAMP + bi] = 1.0f;   // all writers store 1.0f — benign race
    }
}

// ---------------------------------------------------------------------------
// z_q gather (back to b,c,h,w,d layout) + loss sum of squares
__global__ void zq_kernel(const float* __restrict__ z,
                          const float* __restrict__ emb,
                          float* __restrict__ out) {
    __shared__ int sidx[32];
    __shared__ double red[256];
    int tid = threadIdx.x;
    int t0 = blockIdx.x * 32;
    int b = t0 >> 15, s0 = t0 & 32767;
    if (tid < 32) sidx[tid] = g_idx[t0 + tid];
    __syncthreads();
    size_t zbase = ((size_t)b << 23) + s0;
    double acc = 0.0;
    for (int rep = 0; rep < 32; rep++) {
        int lin = rep * 256 + tid;
        int c = lin >> 5;
        int tok = lin & 31;
        float q = emb[(size_t)sidx[tok] * EDIM + c];
        size_t addr = zbase + ((size_t)c << 15) + tok;
        float zv = z[addr];
        out[OFF_ZQ + addr] = q;
        float d = q - zv;
        acc += (double)d * (double)d;
    }
    red[tid] = acc;
    __syncthreads();
    for (int s = 128; s > 0; s >>= 1) {
        if (tid < s) red[tid] += red[tid + s];
        __syncthreads();
    }
    if (tid == 0) atomicAdd(&g_loss_acc, red[0]);
}

// ---------------------------------------------------------------------------
// Codebook self-distance matrix (1024x1024, K=256) -> g_cd
__global__ void __launch_bounds__(256)
cd_kernel(const float* __restrict__ emb) {
    __shared__ float As[16][128];
    __shared__ float Bs[16][128];
    int tid = threadIdx.x;
    int tx = tid & 15, ty = tid >> 4;
    int i0 = blockIdx.y * 128, j0 = blockIdx.x * 128;

    float acc[8][8];
#pragma unroll
    for (int i = 0; i < 8; i++)
#pragma unroll
        for (int j = 0; j < 8; j++) acc[i][j] = 0.0f;

    for (int kc = 0; kc < 16; kc++) {
        int k0 = kc * 16;
        __syncthreads();
        {
            int n = tid & 127;
            int qb = (tid >> 7) * 2;
#pragma unroll
            for (int w = 0; w < 2; w++) {
                int q = qb + w;
                float4 v = *(const float4*)(emb + (size_t)(i0 + n) * EDIM + k0 + q * 4);
                As[q * 4 + 0][n] = v.x; As[q * 4 + 1][n] = v.y;
                As[q * 4 + 2][n] = v.z; As[q * 4 + 3][n] = v.w;
                float4 u = *(const float4*)(emb + (size_t)(j0 + n) * EDIM + k0 + q * 4);
                Bs[q * 4 + 0][n] = u.x; Bs[q * 4 + 1][n] = u.y;
                Bs[q * 4 + 2][n] = u.z; Bs[q * 4 + 3][n] = u.w;
            }
        }
        __syncthreads();
#pragma unroll
        for (int kk = 0; kk < 16; kk++) {
            float a[8], bb[8];
            float4 a0 = *(float4*)&As[kk][ty * 8];
            float4 a1 = *(float4*)&As[kk][ty * 8 + 4];
            a[0] = a0.x; a[1] = a0.y; a[2] = a0.z; a[3] = a0.w;
            a[4] = a1.x; a[5] = a1.y; a[6] = a1.z; a[7] = a1.w;
            float4 b0 = *(float4*)&Bs[kk][tx * 8];
            float4 b1 = *(float4*)&Bs[kk][tx * 8 + 4];
            bb[0] = b0.x; bb[1] = b0.y; bb[2] = b0.z; bb[3] = b0.w;
            bb[4] = b1.x; bb[5] = b1.y; bb[6] = b1.z; bb[7] = b1.w;
#pragma unroll
            for (int i = 0; i < 8; i++)
#pragma unroll
                for (int j = 0; j < 8; j++)
                    acc[i][j] = fmaf(a[i], bb[j], acc[i][j]);
        }
    }
#pragma unroll
    for (int i = 0; i < 8; i++) {
        int gi = i0 + ty * 8 + i;
        float ei = g_ee[gi];
#pragma unroll
        for (int j = 0; j < 8; j++) {
            int gj = j0 + tx * 8 + j;
            float d = __fadd_rn(__fadd_rn(ei, g_ee[gj]), -2.0f * acc[i][j]);
            g_cd[(size_t)gi * NE + gj] = d;
        }
    }
}

// per-row: two smallest (== per-column by symmetry) + variance (ddof=1)
__global__ void cdstats_kernel() {
    __shared__ float  s1[256], s2[256];
    __shared__ double ds[256], dq[256];
    int r = blockIdx.x, tid = threadIdx.x;
    const float* row = g_cd + (size_t)r * NE;
    float a = 3.4e38f, b2 = 3.4e38f;
    double sm = 0.0, sq = 0.0;
    for (int j = tid; j < NE; j += 256) {
        float v = row[j];
        sm += v;
        sq += (double)v * v;
        if (v < a) { b2 = a; a = v; }
        else if (v < b2) { b2 = v; }
    }
    s1[tid] = a; s2[tid] = b2; ds[tid] = sm; dq[tid] = sq;
    __syncthreads();
    for (int s = 128; s > 0; s >>= 1) {
        if (tid < s) {
            float x1 = s1[tid], x2 = s2[tid];
            float y1 = s1[tid + s], y2 = s2[tid + s];
            s1[tid] = fminf(x1, y1);
            s2[tid] = fminf(fmaxf(x1, y1), fminf(x2, y2));
            ds[tid] += ds[tid + s];
            dq[tid] += dq[tid + s];
        }
        __syncthreads();
    }
    if (tid == 0) {
        atomicAdd(&g_min2_acc, (double)s2[0]);
        double S = ds[0], Q = dq[0];
        double var = (Q - S * S / 1024.0) / 1023.0;
        atomicAdd(&g_var_acc, var);
    }
}

__global__ void fin_kernel(float* __restrict__ out) {
    float m = (float)(g_loss_acc / 16777216.0);
    out[OFF_LOSS] = 0.2f * m + m;
    out[OFF_MCD] = (float)(g_min2_acc / 1024.0);
    out[OFF_MCV] = (float)(g_var_acc / 1024.0);
}

// ---------------------------------------------------------------------------
extern "C" void kernel_launch(void* const* d_in, const int* in_sizes, int n_in,
                              void* d_out, int out_size) {
    const float* z   = (const float*)d_in[0];
    const float* emb = (const float*)d_in[1];
    float* out = (float*)d_out;

    init_kernel<<<8, 256>>>(out);
    ee_kernel<<<4, 256>>>(emb);
    zz_kernel<<<256, 256>>>(z);
    dist_kernel<<<512, 128>>>(z, emb, out);
    zq_kernel<<<2048, 256>>>(z, emb, out);
    cd_kernel<<<dim3(8, 8), 256>>>(emb);
    cdstats_kernel<<<1024, 256>>>();
    fin_kernel<<<1, 1>>>(out);
}

// round 3
// speedup vs baseline: 1.2882x; 1.2882x over previous
#include <cuda_runtime.h>

#define NTOK 65536
#define EDIM 256
#define NE   1024

#define OFF_ZQ   0
#define OFF_LOSS 16777216
#define OFF_IDX  16777217
#define OFF_SAMP 16842753
#define OFF_MCD  16844801
#define OFF_MCV  16844802

typedef unsigned long long ull;

static __device__ float  g_zz[NTOK];
static __device__ float  g_ee[NE];
static __device__ int    g_idx[NTOK];
static __device__ float  g_cd[NE * NE];
static __device__ double g_loss_acc;
static __device__ double g_min2_acc;
static __device__ double g_var_acc;

// Packed dual-fp32 FMA (Blackwell; PTX-only)
__device__ __forceinline__ ull ffma2(ull a, ull b, ull c) {
    ull d;
    asm("fma.rn.f32x2 %0, %1, %2, %3;" : "=l"(d) : "l"(a), "l"(b), "l"(c));
    return d;
}

__device__ __forceinline__ void cp_async16(void* sdst, const void* gsrc) {
    unsigned sa = (unsigned)__cvta_generic_to_shared(sdst);
    asm volatile("cp.async.ca.shared.global [%0], [%1], 16;\n" ::
                 "r"(sa), "l"(gsrc));
}
__device__ __forceinline__ void cp_commit() {
    asm volatile("cp.async.commit_group;\n");
}
__device__ __forceinline__ void cp_wait0() {
    asm volatile("cp.async.wait_group 0;\n" ::: "memory");
}

// ---------------------------------------------------------------------------
__global__ void init_kernel(float* __restrict__ out) {
    int i = blockIdx.x * blockDim.x + threadIdx.x;
    if (i < 2048) out[OFF_SAMP + i] = 0.0f;
    if (i == 0) { g_loss_acc = 0.0; g_min2_acc = 0.0; g_var_acc = 0.0; }
}

__global__ void ee_kernel(const float* __restrict__ emb) {
    int n = blockIdx.x * blockDim.x + threadIdx.x;
    if (n >= NE) return;
    const float* r = emb + (size_t)n * EDIM;
    float acc = 0.0f;
    for (int c = 0; c < EDIM; c++) { float v = r[c]; acc = fmaf(v, v, acc); }
    g_ee[n] = acc;
}

__global__ void zz_kernel(const float* __restrict__ z) {
    int t = blockIdx.x * blockDim.x + threadIdx.x;
    int b = t >> 15, s = t & 32767;
    const float* base = z + ((size_t)b << 23) + s;
    float acc = 0.0f;
#pragma unroll 8
    for (int c = 0; c < EDIM; c++) {
        float v = base[(size_t)c << 15];
        acc = fmaf(v, v, acc);
    }
    g_zz[t] = acc;
}

// ---------------------------------------------------------------------------
// Distance GEMM + argmin. Block: 128 tokens x 1024 codes (8 tiles of 128).
// 128 threads: tx in [0,8) owns codes j*8+tx (j=0..15), ty in [0,16) owns
// 8 tokens as 4 f32x2 pairs. Double-buffered smem, cp.async A-staging,
// reg-prefetched B-staging, one sync per k-chunk.
// Numerics identical to the R2-passing kernel (k accumulated sequentially).
__global__ void __launch_bounds__(128, 2)
dist_kernel(const float* __restrict__ z, const float* __restrict__ emb,
            float* __restrict__ out) {
    extern __shared__ char smem_raw[];
    // [0      , 16384): As[2][16][128] float   (A: z tile, k-major)
    // [16384  , 49152): Bs[2][16][128] ull     (B: emb tile, duplicated pairs)
    float (*As)[16][128] = (float(*)[16][128])smem_raw;
    ull   (*Bs)[16][128] = (ull(*)[16][128])(smem_raw + 16384);

    int tid = threadIdx.x;
    int tx = tid & 7;
    int ty = tid >> 3;
    int t0 = blockIdx.x * 128;
    int b = t0 >> 15, s0 = t0 & 32767;
    const float* zb = z + ((size_t)b << 23) + s0;
    const float* embrow = emb + (size_t)tid * EDIM;  // row (n0+tid) set per nt

    float tzz[8];
#pragma unroll
    for (int i = 0; i < 8; i++) tzz[i] = g_zz[t0 + ty * 8 + i];

    float best[8];
    int   bidx[8];
#pragma unroll
    for (int i = 0; i < 8; i++) { best[i] = 3.4e38f; bidx[i] = 0; }

    // cp.async A staging geometry: 4 chunks of 16B per thread per kc
    int ca_row = tid >> 3;            // reuse: chunk linear = c*128+tid
    (void)ca_row;

    for (int nt = 0; nt < 8; nt++) {
        int n0 = nt * 128;
        const float* brow = embrow + (size_t)n0 * EDIM;

        ull acc[4][16];
#pragma unroll
        for (int p = 0; p < 4; p++)
#pragma unroll
            for (int j = 0; j < 16; j++) acc[p][j] = 0ull;

        float bq[16];

        // ---- prologue: stage kc=0 into buffer 0 ----
        {
            const float4* src = (const float4*)(brow);
            float4 v0 = src[0], v1 = src[1], v2 = src[2], v3 = src[3];
            bq[0]=v0.x; bq[1]=v0.y; bq[2]=v0.z; bq[3]=v0.w;
            bq[4]=v1.x; bq[5]=v1.y; bq[6]=v1.z; bq[7]=v1.w;
            bq[8]=v2.x; bq[9]=v2.y; bq[10]=v2.z; bq[11]=v2.w;
            bq[12]=v3.x; bq[13]=v3.y; bq[14]=v3.z; bq[15]=v3.w;
#pragma unroll
            for (int c = 0; c < 4; c++) {
                int lin = c * 128 + tid;
                int row = lin >> 5, col = (lin & 31) * 4;
                cp_async16(&As[0][row][col],
                           zb + ((size_t)row << 15) + col);
            }
            cp_commit();
#pragma unroll
            for (int q = 0; q < 16; q++) {
                unsigned u = __float_as_uint(bq[q]);
                Bs[0][q][tid] = ((ull)u << 32) | u;
            }
            cp_wait0();
        }
        __syncthreads();

        for (int kc = 0; kc < 16; kc++) {
            int buf = kc & 1;
            // ---- issue staging for kc+1 (latency hidden under compute) ----
            if (kc < 15) {
                const float4* src = (const float4*)(brow + (kc + 1) * 16);
                float4 v0 = src[0], v1 = src[1], v2 = src[2], v3 = src[3];
                bq[0]=v0.x; bq[1]=v0.y; bq[2]=v0.z; bq[3]=v0.w;
                bq[4]=v1.x; bq[5]=v1.y; bq[6]=v1.z; bq[7]=v1.w;
                bq[8]=v2.x; bq[9]=v2.y; bq[10]=v2.z; bq[11]=v2.w;
                bq[12]=v3.x; bq[13]=v3.y; bq[14]=v3.z; bq[15]=v3.w;
#pragma unroll
                for (int c = 0; c < 4; c++) {
                    int lin = c * 128 + tid;
                    int row = lin >> 5, col = (lin & 31) * 4;
                    cp_async16(&As[buf ^ 1][row][col],
                               zb + ((size_t)((kc + 1) * 16 + row) << 15) + col);
                }
                cp_commit();
            }
            // ---- compute kc from buf ----
#pragma unroll
            for (int kk = 0; kk < 16; kk++) {
                ull a2[4];
#pragma unroll
                for (int p = 0; p < 4; p++)
                    a2[p] = *(const ull*)&As[buf][kk][ty * 8 + 2 * p];
#pragma unroll
                for (int j = 0; j < 16; j++) {
                    ull bv = Bs[buf][kk][j * 8 + tx];
#pragma unroll
                    for (int p = 0; p < 4; p++)
                        acc[p][j] = ffma2(a2[p], bv, acc[p][j]);
                }
            }
            // ---- finish staging for kc+1 ----
            if (kc < 15) {
#pragma unroll
                for (int q = 0; q < 16; q++) {
                    unsigned u = __float_as_uint(bq[q]);
                    Bs[buf ^ 1][q][tid] = ((ull)u << 32) | u;
                }
                cp_wait0();
            }
            __syncthreads();
        }

        // ---- epilogue: d = fl(fl(zz+ee) - 2*dot), lowest-index tiebreak ----
#pragma unroll
        for (int j = 0; j < 16; j++) {
            int n = n0 + j * 8 + tx;
            float ev = g_ee[n];
#pragma unroll
            for (int p = 0; p < 4; p++) {
                float2 av = *(float2*)&acc[p][j];
                {
                    int i = 2 * p;
                    float d = __fadd_rn(__fadd_rn(tzz[i], ev), -2.0f * av.x);
                    if (d < best[i] || (d == best[i] && n < bidx[i])) {
                        best[i] = d; bidx[i] = n;
                    }
                }
                {
                    int i = 2 * p + 1;
                    float d = __fadd_rn(__fadd_rn(tzz[i], ev), -2.0f * av.y);
                    if (d < best[i] || (d == best[i] && n < bidx[i])) {
                        best[i] = d; bidx[i] = n;
                    }
                }
            }
        }
    }

    // ---- cross-thread reduction over tx (8 candidates per token) ----
    __syncthreads();   // all compute done; reuse As area for reduction
    float* rv = (float*)smem_raw;            // [128][8]
    int*   ri = (int*)(smem_raw + 4096);     // [128][8]
#pragma unroll
    for (int i = 0; i < 8; i++) {
        rv[(ty * 8 + i) * 8 + tx] = best[i];
        ri[(ty * 8 + i) * 8 + tx] = bidx[i];
    }
    __syncthreads();
    {
        float bv = rv[tid * 8 + 0];
        int   bi = ri[tid * 8 + 0];
#pragma unroll
        for (int x = 1; x < 8; x++) {
            float v = rv[tid * 8 + x];
            int   id = ri[tid * 8 + x];
            if (v < bv || (v == bv && id < bi)) { bv = v; bi = id; }
        }
        int t = t0 + tid;
        g_idx[t] = bi;
        out[OFF_IDX + t] = (float)bi;
        out[OFF_SAMP + bi] = 1.0f;   // all writers store 1.0f — benign race
    }
}

// ---------------------------------------------------------------------------
__global__ void zq_kernel(const float* __restrict__ z,
                          const float* __restrict__ emb,
                          float* __restrict__ out) {
    __shared__ int sidx[32];
    __shared__ double red[256];
    int tid = threadIdx.x;
    int t0 = blockIdx.x * 32;
    int b = t0 >> 15, s0 = t0 & 32767;
    if (tid < 32) sidx[tid] = g_idx[t0 + tid];
    __syncthreads();
    size_t zbase = ((size_t)b << 23) + s0;
    double acc = 0.0;
    for (int rep = 0; rep < 32; rep++) {
        int lin = rep * 256 + tid;
        int c = lin >> 5;
        int tok = lin & 31;
        float q = emb[(size_t)sidx[tok] * EDIM + c];
        size_t addr = zbase + ((size_t)c << 15) + tok;
        float zv = z[addr];
        out[OFF_ZQ + addr] = q;
        float d = q - zv;
        acc += (double)d * (double)d;
    }
    red[tid] = acc;
    __syncthreads();
    for (int s = 128; s > 0; s >>= 1) {
        if (tid < s) red[tid] += red[tid + s];
        __syncthreads();
    }
    if (tid == 0) atomicAdd(&g_loss_acc, red[0]);
}

// ---------------------------------------------------------------------------
__global__ void __launch_bounds__(256)
cd_kernel(const float* __restrict__ emb) {
    __shared__ float As[16][128];
    __shared__ float Bs[16][128];
    int tid = threadIdx.x;
    int tx = tid & 15, ty = tid >> 4;
    int i0 = blockIdx.y * 128, j0 = blockIdx.x * 128;

    float acc[8][8];
#pragma unroll
    for (int i = 0; i < 8; i++)
#pragma unroll
        for (int j = 0; j < 8; j++) acc[i][j] = 0.0f;

    for (int kc = 0; kc < 16; kc++) {
        int k0 = kc * 16;
        __syncthreads();
        {
            int n = tid & 127;
            int qb = (tid >> 7) * 2;
#pragma unroll
            for (int w = 0; w < 2; w++) {
                int q = qb + w;
                float4 v = *(const float4*)(emb + (size_t)(i0 + n) * EDIM + k0 + q * 4);
                As[q * 4 + 0][n] = v.x; As[q * 4 + 1][n] = v.y;
                As[q * 4 + 2][n] = v.z; As[q * 4 + 3][n] = v.w;
                float4 u = *(const float4*)(emb + (size_t)(j0 + n) * EDIM + k0 + q * 4);
                Bs[q * 4 + 0][n] = u.x; Bs[q * 4 + 1][n] = u.y;
                Bs[q * 4 + 2][n] = u.z; Bs[q * 4 + 3][n] = u.w;
            }
        }
        __syncthreads();
#pragma unroll
        for (int kk = 0; kk < 16; kk++) {
            float a[8], bb[8];
            float4 a0 = *(float4*)&As[kk][ty * 8];
            float4 a1 = *(float4*)&As[kk][ty * 8 + 4];
            a[0] = a0.x; a[1] = a0.y; a[2] = a0.z; a[3] = a0.w;
            a[4] = a1.x; a[5] = a1.y; a[6] = a1.z; a[7] = a1.w;
            float4 b0 = *(float4*)&Bs[kk][tx * 8];
            float4 b1 = *(float4*)&Bs[kk][tx * 8 + 4];
            bb[0] = b0.x; bb[1] = b0.y; bb[2] = b0.z; bb[3] = b0.w;
            bb[4] = b1.x; bb[5] = b1.y; bb[6] = b1.z; bb[7] = b1.w;
#pragma unroll
            for (int i = 0; i < 8; i++)
#pragma unroll
                for (int j = 0; j < 8; j++)
                    acc[i][j] = fmaf(a[i], bb[j], acc[i][j]);
        }
    }
#pragma unroll
    for (int i = 0; i < 8; i++) {
        int gi = i0 + ty * 8 + i;
        float ei = g_ee[gi];
#pragma unroll
        for (int j = 0; j < 8; j++) {
            int gj = j0 + tx * 8 + j;
            float d = __fadd_rn(__fadd_rn(ei, g_ee[gj]), -2.0f * acc[i][j]);
            g_cd[(size_t)gi * NE + gj] = d;
        }
    }
}

__global__ void cdstats_kernel() {
    __shared__ float  s1[256], s2[256];
    __shared__ double ds[256], dq[256];
    int r = blockIdx.x, tid = threadIdx.x;
    const float* row = g_cd + (size_t)r * NE;
    float a = 3.4e38f, b2 = 3.4e38f;
    double sm = 0.0, sq = 0.0;
    for (int j = tid; j < NE; j += 256) {
        float v = row[j];
        sm += v;
        sq += (double)v * v;
        if (v < a) { b2 = a; a = v; }
        else if (v < b2) { b2 = v; }
    }
    s1[tid] = a; s2[tid] = b2; ds[tid] = sm; dq[tid] = sq;
    __syncthreads();
    for (int s = 128; s > 0; s >>= 1) {
        if (tid < s) {
            float x1 = s1[tid], x2 = s2[tid];
            float y1 = s1[tid + s], y2 = s2[tid + s];
            s1[tid] = fminf(x1, y1);
            s2[tid] = fminf(fmaxf(x1, y1), fminf(x2, y2));
            ds[tid] += ds[tid + s];
            dq[tid] += dq[tid + s];
        }
        __syncthreads();
    }
    if (tid == 0) {
        atomicAdd(&g_min2_acc, (double)s2[0]);
        double S = ds[0], Q = dq[0];
        double var = (Q - S * S / 1024.0) / 1023.0;
        atomicAdd(&g_var_acc, var);
    }
}

__global__ void fin_kernel(float* __restrict__ out) {
    float m = (float)(g_loss_acc / 16777216.0);
    out[OFF_LOSS] = 0.2f * m + m;
    out[OFF_MCD] = (float)(g_min2_acc / 1024.0);
    out[OFF_MCV] = (float)(g_var_acc / 1024.0);
}

// ---------------------------------------------------------------------------
extern "C" void kernel_launch(void* const* d_in, const int* in_sizes, int n_in,
                              void* d_out, int out_size) {
    const float* z   = (const float*)d_in[0];
    const float* emb = (const float*)d_in[1];
    float* out = (float*)d_out;

    cudaFuncSetAttribute(dist_kernel,
                         cudaFuncAttributeMaxDynamicSharedMemorySize, 49152);

    init_kernel<<<8, 256>>>(out);
    ee_kernel<<<4, 256>>>(emb);
    zz_kernel<<<256, 256>>>(z);
    dist_kernel<<<512, 128, 49152>>>(z, emb, out);
    zq_kernel<<<2048, 256>>>(z, emb, out);
    cd_kernel<<<dim3(8, 8), 256>>>(emb);
    cdstats_kernel<<<1024, 256>>>();
    fin_kernel<<<1, 1>>>(out);
}

// round 4
// speedup vs baseline: 1.3429x; 1.0424x over previous
#include <cuda_runtime.h>

#define NTOK 65536
#define EDIM 256
#define NE   1024

#define OFF_ZQ   0
#define OFF_LOSS 16777216
#define OFF_IDX  16777217
#define OFF_SAMP 16842753
#define OFF_MCD  16844801
#define OFF_MCV  16844802

typedef unsigned long long ull;

static __device__ float  g_zz[NTOK];
static __device__ float  g_ee[NE];
static __device__ int    g_idx[NTOK];
static __device__ float  g_cd[NE * NE];
static __device__ double g_loss_acc;
static __device__ double g_min2_acc;
static __device__ double g_var_acc;

// Packed dual-fp32 FMA (Blackwell; PTX-only)
__device__ __forceinline__ ull ffma2(ull a, ull b, ull c) {
    ull d;
    asm("fma.rn.f32x2 %0, %1, %2, %3;" : "=l"(d) : "l"(a), "l"(b), "l"(c));
    return d;
}

__device__ __forceinline__ void cp_async16(void* sdst, const void* gsrc) {
    unsigned sa = (unsigned)__cvta_generic_to_shared(sdst);
    asm volatile("cp.async.ca.shared.global [%0], [%1], 16;\n" ::
                 "r"(sa), "l"(gsrc));
}
__device__ __forceinline__ void cp_commit() {
    asm volatile("cp.async.commit_group;\n");
}
__device__ __forceinline__ void cp_wait0() {
    asm volatile("cp.async.wait_group 0;\n" ::: "memory");
}

// ---------------------------------------------------------------------------
__global__ void init_kernel(float* __restrict__ out) {
    int i = blockIdx.x * blockDim.x + threadIdx.x;
    if (i < 2048) out[OFF_SAMP + i] = 0.0f;
    if (i == 0) { g_loss_acc = 0.0; g_min2_acc = 0.0; g_var_acc = 0.0; }
}

__global__ void ee_kernel(const float* __restrict__ emb) {
    int n = blockIdx.x * blockDim.x + threadIdx.x;
    if (n >= NE) return;
    const float* r = emb + (size_t)n * EDIM;
    float acc = 0.0f;
    for (int c = 0; c < EDIM; c++) { float v = r[c]; acc = fmaf(v, v, acc); }
    g_ee[n] = acc;
}

__global__ void zz_kernel(const float* __restrict__ z) {
    int t = blockIdx.x * blockDim.x + threadIdx.x;
    int b = t >> 15, s = t & 32767;
    const float* base = z + ((size_t)b << 23) + s;
    float acc = 0.0f;
#pragma unroll 8
    for (int c = 0; c < EDIM; c++) {
        float v = base[(size_t)c << 15];
        acc = fmaf(v, v, acc);
    }
    g_zz[t] = acc;
}

// ---------------------------------------------------------------------------
// Distance GEMM + argmin. Block tile: 128 tokens x 128 codes (8 nt tiles).
// 256 threads: tx in [0,16) owns codes {j*16+tx}, ty in [0,16) owns 8 tokens
// (4 f32x2 pairs). 64 scalar accumulators/thread -> regs<=128 -> 2 CTAs/SM
// (16 warps). Double-buffered smem, cp.async A-staging, dup-pair B-staging.
// Numerics bit-identical to R2/R3 (k accumulated sequentially, same epilogue).
__global__ void __launch_bounds__(256, 2)
dist_kernel(const float* __restrict__ z, const float* __restrict__ emb,
            float* __restrict__ out) {
    extern __shared__ char smem_raw[];
    // [0      , 16384): As[2][16][128] float  (A: z tile, k-major)
    // [16384  , 49152): Bs[2][16][128] ull    (B: emb tile, duplicated pairs)
    float (*As)[16][128] = (float(*)[16][128])smem_raw;
    ull   (*Bs)[16][128] = (ull(*)[16][128])(smem_raw + 16384);

    int tid = threadIdx.x;
    int tx = tid & 15;
    int ty = tid >> 4;
    int t0 = blockIdx.x * 128;
    int b = t0 >> 15, s0 = t0 & 32767;
    const float* zb = z + ((size_t)b << 23) + s0;
    // B staging: each thread owns half a row: row = tid>>1, half = tid&1
    int brow_i = tid >> 1;
    int bhalf  = tid & 1;
    const float* embrow = emb + (size_t)brow_i * EDIM + bhalf * 8;

    float tzz[8];
#pragma unroll
    for (int i = 0; i < 8; i++) tzz[i] = g_zz[t0 + ty * 8 + i];

    float best[8];
    int   bidx[8];
#pragma unroll
    for (int i = 0; i < 8; i++) { best[i] = 3.4e38f; bidx[i] = 0; }

    for (int nt = 0; nt < 8; nt++) {
        int n0 = nt * 128;
        const float* bsrc = embrow + (size_t)n0 * EDIM;

        ull acc[4][8];
#pragma unroll
        for (int p = 0; p < 4; p++)
#pragma unroll
            for (int j = 0; j < 8; j++) acc[p][j] = 0ull;

        float bq[8];

        // ---- prologue: stage kc=0 into buffer 0 ----
        {
            float4 v0 = *(const float4*)(bsrc);
            float4 v1 = *(const float4*)(bsrc + 4);
            bq[0]=v0.x; bq[1]=v0.y; bq[2]=v0.z; bq[3]=v0.w;
            bq[4]=v1.x; bq[5]=v1.y; bq[6]=v1.z; bq[7]=v1.w;
#pragma unroll
            for (int c = 0; c < 2; c++) {
                int lin = c * 256 + tid;
                int row = lin >> 5, col = (lin & 31) * 4;
                cp_async16(&As[0][row][col], zb + ((size_t)row << 15) + col);
            }
            cp_commit();
#pragma unroll
            for (int q = 0; q < 8; q++) {
                unsigned u = __float_as_uint(bq[q]);
                Bs[0][bhalf * 8 + q][brow_i] = ((ull)u << 32) | u;
            }
            cp_wait0();
        }
        __syncthreads();

        for (int kc = 0; kc < 16; kc++) {
            int buf = kc & 1;
            // ---- issue staging for kc+1 (latency hidden under compute) ----
            if (kc < 15) {
                const float* p1 = bsrc + (kc + 1) * 16;
                float4 v0 = *(const float4*)(p1);
                float4 v1 = *(const float4*)(p1 + 4);
                bq[0]=v0.x; bq[1]=v0.y; bq[2]=v0.z; bq[3]=v0.w;
                bq[4]=v1.x; bq[5]=v1.y; bq[6]=v1.z; bq[7]=v1.w;
#pragma unroll
                for (int c = 0; c < 2; c++) {
                    int lin = c * 256 + tid;
                    int row = lin >> 5, col = (lin & 31) * 4;
                    cp_async16(&As[buf ^ 1][row][col],
                               zb + ((size_t)((kc + 1) * 16 + row) << 15) + col);
                }
                cp_commit();
            }
            // ---- compute kc from buf ----
#pragma unroll
            for (int kk = 0; kk < 16; kk++) {
                ull a2[4];
#pragma unroll
                for (int p = 0; p < 4; p++)
                    a2[p] = *(const ull*)&As[buf][kk][ty * 8 + 2 * p];
#pragma unroll
                for (int j = 0; j < 8; j++) {
                    ull bv = Bs[buf][kk][j * 16 + tx];
#pragma unroll
                    for (int p = 0; p < 4; p++)
                        acc[p][j] = ffma2(a2[p], bv, acc[p][j]);
                }
            }
            // ---- finish staging for kc+1 ----
            if (kc < 15) {
#pragma unroll
                for (int q = 0; q < 8; q++) {
                    unsigned u = __float_as_uint(bq[q]);
                    Bs[buf ^ 1][bhalf * 8 + q][brow_i] = ((ull)u << 32) | u;
                }
                cp_wait0();
            }
            __syncthreads();
        }

        // ---- epilogue: d = fl(fl(zz+ee) - 2*dot), lowest-index tiebreak ----
#pragma unroll
        for (int j = 0; j < 8; j++) {
            int n = n0 + j * 16 + tx;
            float ev = g_ee[n];
#pragma unroll
            for (int p = 0; p < 4; p++) {
                float2 av = *(float2*)&acc[p][j];
                {
                    int i = 2 * p;
                    float d = __fadd_rn(__fadd_rn(tzz[i], ev), -2.0f * av.x);
                    if (d < best[i] || (d == best[i] && n < bidx[i])) {
                        best[i] = d; bidx[i] = n;
                    }
                }
                {
                    int i = 2 * p + 1;
                    float d = __fadd_rn(__fadd_rn(tzz[i], ev), -2.0f * av.y);
                    if (d < best[i] || (d == best[i] && n < bidx[i])) {
                        best[i] = d; bidx[i] = n;
                    }
                }
            }
        }
    }

    // ---- cross-thread reduction over tx (16 candidates per token) ----
    float* rv = (float*)smem_raw;             // [128][16] = 8KB
    int*   ri = (int*)(smem_raw + 8192);      // [128][16] = 8KB
#pragma unroll
    for (int i = 0; i < 8; i++) {
        rv[(ty * 8 + i) * 16 + tx] = best[i];
        ri[(ty * 8 + i) * 16 + tx] = bidx[i];
    }
    __syncthreads();
    if (tid < 128) {
        float bv = rv[tid * 16 + 0];
        int   bi = ri[tid * 16 + 0];
#pragma unroll
        for (int x = 1; x < 16; x++) {
            float v = rv[tid * 16 + x];
            int   id = ri[tid * 16 + x];
            if (v < bv || (v == bv && id < bi)) { bv = v; bi = id; }
        }
        int t = t0 + tid;
        g_idx[t] = bi;
        out[OFF_IDX + t] = (float)bi;
        out[OFF_SAMP + bi] = 1.0f;   // all writers store 1.0f — benign race
    }
}

// ---------------------------------------------------------------------------
__global__ void zq_kernel(const float* __restrict__ z,
                          const float* __restrict__ emb,
                          float* __restrict__ out) {
    __shared__ int sidx[32];
    __shared__ double red[256];
    int tid = threadIdx.x;
    int t0 = blockIdx.x * 32;
    int b = t0 >> 15, s0 = t0 & 32767;
    if (tid < 32) sidx[tid] = g_idx[t0 + tid];
    __syncthreads();
    size_t zbase = ((size_t)b << 23) + s0;
    double acc = 0.0;
    for (int rep = 0; rep < 32; rep++) {
        int lin = rep * 256 + tid;
        int c = lin >> 5;
        int tok = lin & 31;
        float q = emb[(size_t)sidx[tok] * EDIM + c];
        size_t addr = zbase + ((size_t)c << 15) + tok;
        float zv = z[addr];
        out[OFF_ZQ + addr] = q;
        float d = q - zv;
        acc += (double)d * (double)d;
    }
    red[tid] = acc;
    __syncthreads();
    for (int s = 128; s > 0; s >>= 1) {
        if (tid < s) red[tid] += red[tid + s];
        __syncthreads();
    }
    if (tid == 0) atomicAdd(&g_loss_acc, red[0]);
}

// ---------------------------------------------------------------------------
__global__ void __launch_bounds__(256)
cd_kernel(const float* __restrict__ emb) {
    __shared__ float As[16][128];
    __shared__ float Bs[16][128];
    int tid = threadIdx.x;
    int tx = tid & 15, ty = tid >> 4;
    int i0 = blockIdx.y * 128, j0 = blockIdx.x * 128;

    float acc[8][8];
#pragma unroll
    for (int i = 0; i < 8; i++)
#pragma unroll
        for (int j = 0; j < 8; j++) acc[i][j] = 0.0f;

    for (int kc = 0; kc < 16; kc++) {
        int k0 = kc * 16;
        __syncthreads();
        {
            int n = tid & 127;
            int qb = (tid >> 7) * 2;
#pragma unroll
            for (int w = 0; w < 2; w++) {
                int q = qb + w;
                float4 v = *(const float4*)(emb + (size_t)(i0 + n) * EDIM + k0 + q * 4);
                As[q * 4 + 0][n] = v.x; As[q * 4 + 1][n] = v.y;
                As[q * 4 + 2][n] = v.z; As[q * 4 + 3][n] = v.w;
                float4 u = *(const float4*)(emb + (size_t)(j0 + n) * EDIM + k0 + q * 4);
                Bs[q * 4 + 0][n] = u.x; Bs[q * 4 + 1][n] = u.y;
                Bs[q * 4 + 2][n] = u.z; Bs[q * 4 + 3][n] = u.w;
            }
        }
        __syncthreads();
#pragma unroll
        for (int kk = 0; kk < 16; kk++) {
            float a[8], bb[8];
            float4 a0 = *(float4*)&As[kk][ty * 8];
            float4 a1 = *(float4*)&As[kk][ty * 8 + 4];
            a[0] = a0.x; a[1] = a0.y; a[2] = a0.z; a[3] = a0.w;
            a[4] = a1.x; a[5] = a1.y; a[6] = a1.z; a[7] = a1.w;
            float4 b0 = *(float4*)&Bs[kk][tx * 8];
            float4 b1 = *(float4*)&Bs[kk][tx * 8 + 4];
            bb[0] = b0.x; bb[1] = b0.y; bb[2] = b0.z; bb[3] = b0.w;
            bb[4] = b1.x; bb[5] = b1.y; bb[6] = b1.z; bb[7] = b1.w;
#pragma unroll
            for (int i = 0; i < 8; i++)
#pragma unroll
                for (int j = 0; j < 8; j++)
                    acc[i][j] = fmaf(a[i], bb[j], acc[i][j]);
        }
    }
#pragma unroll
    for (int i = 0; i < 8; i++) {
        int gi = i0 + ty * 8 + i;
        float ei = g_ee[gi];
#pragma unroll
        for (int j = 0; j < 8; j++) {
            int gj = j0 + tx * 8 + j;
            float d = __fadd_rn(__fadd_rn(ei, g_ee[gj]), -2.0f * acc[i][j]);
            g_cd[(size_t)gi * NE + gj] = d;
        }
    }
}

__global__ void cdstats_kernel() {
    __shared__ float  s1[256], s2[256];
    __shared__ double ds[256], dq[256];
    int r = blockIdx.x, tid = threadIdx.x;
    const float* row = g_cd + (size_t)r * NE;
    float a = 3.4e38f, b2 = 3.4e38f;
    double sm = 0.0, sq = 0.0;
    for (int j = tid; j < NE; j += 256) {
        float v = row[j];
        sm += v;
        sq += (double)v * v;
        if (v < a) { b2 = a; a = v; }
        else if (v < b2) { b2 = v; }
    }
    s1[tid] = a; s2[tid] = b2; ds[tid] = sm; dq[tid] = sq;
    __syncthreads();
    for (int s = 128; s > 0; s >>= 1) {
        if (tid < s) {
            float x1 = s1[tid], x2 = s2[tid];
            float y1 = s1[tid + s], y2 = s2[tid + s];
            s1[tid] = fminf(x1, y1);
            s2[tid] = fminf(fmaxf(x1, y1), fminf(x2, y2));
            ds[tid] += ds[tid + s];
            dq[tid] += dq[tid + s];
        }
        __syncthreads();
    }
    if (tid == 0) {
        atomicAdd(&g_min2_acc, (double)s2[0]);
        double S = ds[0], Q = dq[0];
        double var = (Q - S * S / 1024.0) / 1023.0;
        atomicAdd(&g_var_acc, var);
    }
}

__global__ void fin_kernel(float* __restrict__ out) {
    float m = (float)(g_loss_acc / 16777216.0);
    out[OFF_LOSS] = 0.2f * m + m;
    out[OFF_MCD] = (float)(g_min2_acc / 1024.0);
    out[OFF_MCV] = (float)(g_var_acc / 1024.0);
}

// ---------------------------------------------------------------------------
extern "C" void kernel_launch(void* const* d_in, const int* in_sizes, int n_in,
                              void* d_out, int out_size) {
    const float* z   = (const float*)d_in[0];
    const float* emb = (const float*)d_in[1];
    float* out = (float*)d_out;

    cudaFuncSetAttribute(dist_kernel,
                         cudaFuncAttributeMaxDynamicSharedMemorySize, 49152);

    init_kernel<<<8, 256>>>(out);
    ee_kernel<<<4, 256>>>(emb);
    zz_kernel<<<256, 256>>>(z);
    dist_kernel<<<512, 256, 49152>>>(z, emb, out);
    zq_kernel<<<2048, 256>>>(z, emb, out);
    cd_kernel<<<dim3(8, 8), 256>>>(emb);
    cdstats_kernel<<<1024, 256>>>();
    fin_kernel<<<1, 1>>>(out);
}